// round 6
// baseline (speedup 1.0000x reference)
#include <cuda_runtime.h>
#include <cuda_bf16.h>
#include <math.h>
#include <stdint.h>

// Problem shape (fixed): x[4096,2048] fp32, targets[4096] i32, sub[4096] i32.
#define N_ROWS 4096
#define D_DIM  2048

#define MARGIN_1 1.0f
#define MARGIN_2 1.5f
#define ALPHA_1  2.4f
#define ALPHA_2  2.2f
#define EPS_F    1e-5f

// Scratch (__device__ globals: sanctioned no-alloc workaround)
__device__ __nv_bfloat16 g_xb[(size_t)N_ROWS * D_DIM];  // normalized rows, bf16 (16 MB, L2-resident)
__device__ float g_acc[N_ROWS * 8];
// [0]=sum_pos_intra [1]=cnt_pos_intra [2]=sum_pos_cross [3]=cnt_pos_cross
// [4]=num_neg_intra [5]=den_neg_intra [6]=num_neg_cross [7]=den_neg_cross

// ---------------------------------------------------------------------------
// PTX helpers — sm_80-era ops only (cp.async / ldmatrix / mma.sync).
// NOTE: tcgen05/TMEM is OFF LIMITS: harness compiles at .target sm_103 (no 'a').
// ---------------------------------------------------------------------------
__device__ __forceinline__ uint32_t smem_u32(const void* p) {
    uint32_t a;
    asm("{ .reg .u64 t; cvta.to.shared.u64 t, %1; cvt.u32.u64 %0, t; }" : "=r"(a) : "l"(p));
    return a;
}
__device__ __forceinline__ void cp16(uint32_t dst, const void* src) {
    asm volatile("cp.async.cg.shared.global [%0], [%1], 16;" :: "r"(dst), "l"(src));
}
__device__ __forceinline__ void cp_commit() {
    asm volatile("cp.async.commit_group;" ::: "memory");
}
template <int N>
__device__ __forceinline__ void cp_wait() {
    asm volatile("cp.async.wait_group %0;" :: "n"(N) : "memory");
}
__device__ __forceinline__ void ldsm_x4(uint32_t& r0, uint32_t& r1, uint32_t& r2, uint32_t& r3,
                                        uint32_t addr) {
    asm volatile("ldmatrix.sync.aligned.m8n8.x4.shared.b16 {%0,%1,%2,%3}, [%4];"
        : "=r"(r0), "=r"(r1), "=r"(r2), "=r"(r3) : "r"(addr));
}
__device__ __forceinline__ void mma16816(float* c, const uint32_t* a, uint32_t b0, uint32_t b1) {
    asm volatile("mma.sync.aligned.m16n8k16.row.col.f32.bf16.bf16.f32 "
        "{%0,%1,%2,%3}, {%4,%5,%6,%7}, {%8,%9}, {%0,%1,%2,%3};"
        : "+f"(c[0]), "+f"(c[1]), "+f"(c[2]), "+f"(c[3])
        : "r"(a[0]), "r"(a[1]), "r"(a[2]), "r"(a[3]), "r"(b0), "r"(b1));
}

// 128B-row XOR swizzle (conflict-free for both cp.async stores and ldmatrix reads)
#define SWZ(x) ((x) ^ (((x) >> 3) & 0x70u))

// ---------------------------------------------------------------------------
// Kernel 0: zero accumulators
// ---------------------------------------------------------------------------
__global__ void zero_acc_kernel() {
    int i = blockIdx.x * blockDim.x + threadIdx.x;
    if (i < N_ROWS * 8) g_acc[i] = 0.0f;
}

// ---------------------------------------------------------------------------
// Kernel 1: row L2-normalize + convert to bf16. 1 block/row, 256 threads.
// ---------------------------------------------------------------------------
__global__ __launch_bounds__(256) void normalize_kernel(const float* __restrict__ x) {
    const int row = blockIdx.x;
    const int tid = threadIdx.x;
    const float4* xr = reinterpret_cast<const float4*>(x + (size_t)row * D_DIM);

    float4 v0 = xr[2 * tid];
    float4 v1 = xr[2 * tid + 1];
    float ss = v0.x * v0.x + v0.y * v0.y + v0.z * v0.z + v0.w * v0.w
             + v1.x * v1.x + v1.y * v1.y + v1.z * v1.z + v1.w * v1.w;
    #pragma unroll
    for (int off = 16; off; off >>= 1)
        ss += __shfl_down_sync(0xffffffffu, ss, off);

    __shared__ float red[8];
    __shared__ float s_inv;
    if ((tid & 31) == 0) red[tid >> 5] = ss;
    __syncthreads();
    if (tid == 0) {
        float tot = 0.f;
        #pragma unroll
        for (int w = 0; w < 8; ++w) tot += red[w];
        s_inv = 1.0f / fmaxf(sqrtf(tot), 1e-12f);
    }
    __syncthreads();
    const float inv = s_inv;

    __nv_bfloat162 h[4];
    h[0] = __float22bfloat162_rn(make_float2(v0.x * inv, v0.y * inv));
    h[1] = __float22bfloat162_rn(make_float2(v0.z * inv, v0.w * inv));
    h[2] = __float22bfloat162_rn(make_float2(v1.x * inv, v1.y * inv));
    h[3] = __float22bfloat162_rn(make_float2(v1.z * inv, v1.w * inv));
    uint4 pk;
    pk.x = *reinterpret_cast<uint32_t*>(&h[0]);
    pk.y = *reinterpret_cast<uint32_t*>(&h[1]);
    pk.z = *reinterpret_cast<uint32_t*>(&h[2]);
    pk.w = *reinterpret_cast<uint32_t*>(&h[3]);
    *reinterpret_cast<uint4*>(&g_xb[(size_t)row * D_DIM + tid * 8]) = pk;
}

// ---------------------------------------------------------------------------
// Kernel 2: fused bf16 HMMA Gram tile + masked loss epilogue.
// 128x128 tile/CTA, 256 threads (8 warps = 2x4), warp tile 64x32,
// K chunks of 64 bf16 (128B swizzled rows), cp.async double buffer.
// ---------------------------------------------------------------------------
#define NCHUNK 32          // 2048 / 64
#define TGT_OFF 0
#define SUB_OFF 512
#define AOFF0 1024
#define AOFF1 (1024 + 16384)
#define BOFF0 (1024 + 32768)
#define BOFF1 (1024 + 49152)
#define SMEM_TOTAL (1024 + 65536)

__global__ __launch_bounds__(256, 2) void fused_loss_kernel(
    const int* __restrict__ targets, const int* __restrict__ sub) {

    extern __shared__ char smem[];
    const uint32_t sbase = smem_u32(smem);
    const int tid  = threadIdx.x;
    const int wid  = tid >> 5;
    const int lane = tid & 31;
    const int warp_m = wid & 1;     // 0..1 -> 64 rows each
    const int warp_n = wid >> 1;    // 0..3 -> 32 cols each
    const int row0 = blockIdx.y * 128;
    const int col0 = blockIdx.x * 128;

    int* s_tgt = reinterpret_cast<int*>(smem + TGT_OFF);
    int* s_sub = reinterpret_cast<int*>(smem + SUB_OFF);
    if (tid < 128) {
        s_tgt[tid] = targets[col0 + tid];
        s_sub[tid] = sub[col0 + tid];
    }

    float c[4][4][4];   // [m-atom][n-atom][c-frag]
    #pragma unroll
    for (int i = 0; i < 4; ++i)
        #pragma unroll
        for (int j = 0; j < 4; ++j)
            #pragma unroll
            for (int k = 0; k < 4; ++k) c[i][j][k] = 0.f;

    // ---- cp.async staging: 1024 16B-chunks per operand tile, 4 per thread
    auto load_chunk = [&](int cc, int buf) {
        const uint32_t aOff = buf ? AOFF1 : AOFF0;
        const uint32_t bOff = buf ? BOFF1 : BOFF0;
        #pragma unroll
        for (int i = 0; i < 4; ++i) {
            const int idx = tid + i * 256;      // 0..1023
            const int r  = idx >> 3;            // tile row 0..127
            const int kc = idx & 7;             // 16B chunk 0..7
            const uint32_t soff = SWZ((uint32_t)(idx * 16));
            cp16(sbase + aOff + soff, g_xb + (size_t)(row0 + r) * D_DIM + cc * 64 + kc * 8);
            cp16(sbase + bOff + soff, g_xb + (size_t)(col0 + r) * D_DIM + cc * 64 + kc * 8);
        }
    };

    load_chunk(0, 0);
    cp_commit();

    for (int cc = 0; cc < NCHUNK; ++cc) {
        if (cc < NCHUNK - 1) {
            load_chunk(cc + 1, (cc + 1) & 1);
            cp_commit();
            cp_wait<1>();
        } else {
            cp_wait<0>();
        }
        __syncthreads();

        const uint32_t aBase = sbase + ((cc & 1) ? AOFF1 : AOFF0);
        const uint32_t bBase = sbase + ((cc & 1) ? BOFF1 : BOFF0);

        // ldmatrix lane addressing (same pattern for A and B):
        // lanes 0-7: rows +0..7 (k lo), 8-15: rows +8..15 (k lo),
        // 16-23: rows +0..7 (k hi), 24-31: rows +8..15 (k hi)
        const int lrow = (lane & 7) + ((lane >> 3) & 1) * 8;
        const int lkof = ((lane >> 4) & 1) * 16;

        #pragma unroll
        for (int ks = 0; ks < 4; ++ks) {
            uint32_t a[4][4];
            #pragma unroll
            for (int ma = 0; ma < 4; ++ma) {
                const uint32_t off = (uint32_t)((warp_m * 64 + ma * 16 + lrow) * 128
                                                + ks * 32 + lkof);
                ldsm_x4(a[ma][0], a[ma][1], a[ma][2], a[ma][3], aBase + SWZ(off));
            }
            uint32_t b[2][4];
            #pragma unroll
            for (int nb = 0; nb < 2; ++nb) {
                const uint32_t off = (uint32_t)((warp_n * 32 + nb * 16 + lrow) * 128
                                                + ks * 32 + lkof);
                ldsm_x4(b[nb][0], b[nb][1], b[nb][2], b[nb][3], bBase + SWZ(off));
            }
            #pragma unroll
            for (int ma = 0; ma < 4; ++ma) {
                #pragma unroll
                for (int nb = 0; nb < 2; ++nb) {
                    mma16816(c[ma][nb * 2 + 0], a[ma], b[nb][0], b[nb][2]);
                    mma16816(c[ma][nb * 2 + 1], a[ma], b[nb][1], b[nb][3]);
                }
            }
        }
        __syncthreads();
    }

    // ---------------- epilogue: masked loss terms from register fragments ---
    // c-fragment layout (m16n8): c0=(row g, col t2) c1=(g, t2+1) c2=(g+8, t2) c3=(g+8, t2+1)
    const int gsel = lane >> 2;   // groupID 0..7
    const int tig  = lane & 3;

    #pragma unroll
    for (int ma = 0; ma < 4; ++ma) {
        const int r0 = row0 + warp_m * 64 + ma * 16 + gsel;
        const int r1 = r0 + 8;
        const int ti0 = targets[r0], si0 = sub[r0];
        const int ti1 = targets[r1], si1 = sub[r1];

        float acc[2][8];
        #pragma unroll
        for (int rr = 0; rr < 2; ++rr)
            #pragma unroll
            for (int v = 0; v < 8; ++v) acc[rr][v] = 0.f;

        #pragma unroll
        for (int na = 0; na < 4; ++na) {
            #pragma unroll
            for (int h = 0; h < 2; ++h) {
                const int jj  = warp_n * 32 + na * 8 + tig * 2 + h;
                const int col = col0 + jj;
                const int tj = s_tgt[jj];
                const int sj = s_sub[jj];
                #pragma unroll
                for (int rr = 0; rr < 2; ++rr) {
                    const int row = rr ? r1 : r0;
                    if (col == row) continue;
                    const float cij = c[ma][na][rr * 2 + h];
                    const float d = sqrtf(fmaxf(2.0f - 2.0f * cij, 1e-12f));
                    const bool same  = ((rr ? ti1 : ti0) == tj);
                    const bool intra = ((rr ? si1 : si0) == sj);
                    if (same) {
                        if (intra) { acc[rr][0] += fmaxf(d + (MARGIN_1 - ALPHA_1), 0.f); acc[rr][1] += 1.f; }
                        else       { acc[rr][2] += fmaxf(d + (MARGIN_2 - ALPHA_2), 0.f); acc[rr][3] += 1.f; }
                    } else {
                        const float alpha = intra ? ALPHA_1 : ALPHA_2;
                        const float diff = alpha - d;
                        if (diff > 0.f) {
                            const float w = __expf(diff);   // TVAL = 1
                            if (intra) { acc[rr][4] += diff * w; acc[rr][5] += w; }
                            else       { acc[rr][6] += diff * w; acc[rr][7] += w; }
                        }
                    }
                }
            }
        }

        // reduce across the 4-lane tig group
        #pragma unroll
        for (int rr = 0; rr < 2; ++rr)
            #pragma unroll
            for (int v = 0; v < 8; ++v) {
                acc[rr][v] += __shfl_down_sync(0xffffffffu, acc[rr][v], 2, 4);
                acc[rr][v] += __shfl_down_sync(0xffffffffu, acc[rr][v], 1, 4);
            }

        if (tig == 0) {
            float* a0 = g_acc + (size_t)r0 * 8;
            float* a1 = g_acc + (size_t)r1 * 8;
            #pragma unroll
            for (int v = 0; v < 8; ++v) atomicAdd(a0 + v, acc[0][v]);
            #pragma unroll
            for (int v = 0; v < 8; ++v) atomicAdd(a1 + v, acc[1][v]);
        }
    }
}

// ---------------------------------------------------------------------------
// Kernel 3: per-row combine + mean
// ---------------------------------------------------------------------------
__global__ __launch_bounds__(256) void finalize_kernel(float* __restrict__ out) {
    const int tid = threadIdx.x;
    float sum = 0.f;
    for (int row = tid; row < N_ROWS; row += 256) {
        const float* a = g_acc + (size_t)row * 8;
        sum += a[0] / (a[1] + EPS_F)
             + a[2] / (a[3] + EPS_F)
             + a[4] / (a[5] + EPS_F)
             + a[6] / (a[7] + EPS_F);
    }
    #pragma unroll
    for (int off = 16; off; off >>= 1)
        sum += __shfl_down_sync(0xffffffffu, sum, off);

    __shared__ float red[8];
    if ((tid & 31) == 0) red[tid >> 5] = sum;
    __syncthreads();
    if (tid == 0) {
        float tot = 0.f;
        #pragma unroll
        for (int w = 0; w < 8; ++w) tot += red[w];
        out[0] = tot / (float)N_ROWS;
    }
}

// ---------------------------------------------------------------------------
// Launch
// ---------------------------------------------------------------------------
extern "C" void kernel_launch(void* const* d_in, const int* in_sizes, int n_in,
                              void* d_out, int out_size) {
    const float* x       = (const float*)d_in[0];
    const int*   targets = (const int*)d_in[1];
    const int*   sub     = (const int*)d_in[2];
    float*       out     = (float*)d_out;

    cudaFuncSetAttribute(fused_loss_kernel,
                         cudaFuncAttributeMaxDynamicSharedMemorySize, SMEM_TOTAL);

    zero_acc_kernel<<<(N_ROWS * 8 + 255) / 256, 256>>>();
    normalize_kernel<<<N_ROWS, 256>>>(x);
    dim3 grid(N_ROWS / 128, N_ROWS / 128);
    fused_loss_kernel<<<grid, 256, SMEM_TOTAL>>>(targets, sub);
    finalize_kernel<<<1, 256>>>(out);
}

// round 12
// speedup vs baseline: 1.5760x; 1.5760x over previous
#include <cuda_runtime.h>
#include <cuda_bf16.h>
#include <math.h>
#include <stdint.h>

// Problem shape (fixed): x[4096,2048] fp32, targets[4096] i32, sub[4096] i32.
#define N_ROWS 4096
#define D_DIM  2048

#define MARGIN_1 1.0f
#define MARGIN_2 1.5f
#define ALPHA_1  2.4f
#define ALPHA_2  2.2f
#define EPS_F    1e-5f

// Scratch (__device__ globals: sanctioned no-alloc workaround)
__device__ __nv_bfloat16 g_xb[(size_t)N_ROWS * D_DIM];  // normalized rows, bf16 (16 MB, L2-resident)
__device__ float g_acc[N_ROWS * 8];
// [0]=sum_pos_intra [1]=cnt_pos_intra [2]=sum_pos_cross [3]=cnt_pos_cross
// [4]=num_neg_intra [5]=den_neg_intra [6]=num_neg_cross [7]=den_neg_cross

// ---------------------------------------------------------------------------
// PTX helpers — sm_80-era ops only (tcgen05 is gated off: target is sm_103, no 'a')
// ---------------------------------------------------------------------------
__device__ __forceinline__ uint32_t smem_u32(const void* p) {
    uint32_t a;
    asm("{ .reg .u64 t; cvta.to.shared.u64 t, %1; cvt.u32.u64 %0, t; }" : "=r"(a) : "l"(p));
    return a;
}
__device__ __forceinline__ void cp16(uint32_t dst, const void* src) {
    asm volatile("cp.async.cg.shared.global [%0], [%1], 16;" :: "r"(dst), "l"(src));
}
__device__ __forceinline__ void cp_commit() {
    asm volatile("cp.async.commit_group;" ::: "memory");
}
template <int N>
__device__ __forceinline__ void cp_wait() {
    asm volatile("cp.async.wait_group %0;" :: "n"(N) : "memory");
}
__device__ __forceinline__ void ldsm_x4(uint32_t& r0, uint32_t& r1, uint32_t& r2, uint32_t& r3,
                                        uint32_t addr) {
    asm volatile("ldmatrix.sync.aligned.m8n8.x4.shared.b16 {%0,%1,%2,%3}, [%4];"
        : "=r"(r0), "=r"(r1), "=r"(r2), "=r"(r3) : "r"(addr));
}
__device__ __forceinline__ void mma16816(float* c, const uint32_t* a, uint32_t b0, uint32_t b1) {
    asm volatile("mma.sync.aligned.m16n8k16.row.col.f32.bf16.bf16.f32 "
        "{%0,%1,%2,%3}, {%4,%5,%6,%7}, {%8,%9}, {%0,%1,%2,%3};"
        : "+f"(c[0]), "+f"(c[1]), "+f"(c[2]), "+f"(c[3])
        : "r"(a[0]), "r"(a[1]), "r"(a[2]), "r"(a[3]), "r"(b0), "r"(b1));
}

// 128B-row XOR swizzle for operand staging
#define SWZ(x) ((x) ^ (((x) >> 3) & 0x70u))

// ---------------------------------------------------------------------------
// Kernel 0: zero accumulators + output scalar
// ---------------------------------------------------------------------------
__global__ void zero_acc_kernel(float* __restrict__ out) {
    int i = blockIdx.x * blockDim.x + threadIdx.x;
    if (i < N_ROWS * 8) g_acc[i] = 0.0f;
    if (i == 0) out[0] = 0.0f;
}

// ---------------------------------------------------------------------------
// Kernel 1: row L2-normalize + convert to bf16. 1 block/row, 256 threads.
// ---------------------------------------------------------------------------
__global__ __launch_bounds__(256) void normalize_kernel(const float* __restrict__ x) {
    const int row = blockIdx.x;
    const int tid = threadIdx.x;
    const float4* xr = reinterpret_cast<const float4*>(x + (size_t)row * D_DIM);

    float4 v0 = xr[2 * tid];
    float4 v1 = xr[2 * tid + 1];
    float ss = v0.x * v0.x + v0.y * v0.y + v0.z * v0.z + v0.w * v0.w
             + v1.x * v1.x + v1.y * v1.y + v1.z * v1.z + v1.w * v1.w;
    #pragma unroll
    for (int off = 16; off; off >>= 1)
        ss += __shfl_down_sync(0xffffffffu, ss, off);

    __shared__ float red[8];
    __shared__ float s_inv;
    if ((tid & 31) == 0) red[tid >> 5] = ss;
    __syncthreads();
    if (tid == 0) {
        float tot = 0.f;
        #pragma unroll
        for (int w = 0; w < 8; ++w) tot += red[w];
        s_inv = 1.0f / fmaxf(sqrtf(tot), 1e-12f);
    }
    __syncthreads();
    const float inv = s_inv;

    __nv_bfloat162 h[4];
    h[0] = __float22bfloat162_rn(make_float2(v0.x * inv, v0.y * inv));
    h[1] = __float22bfloat162_rn(make_float2(v0.z * inv, v0.w * inv));
    h[2] = __float22bfloat162_rn(make_float2(v1.x * inv, v1.y * inv));
    h[3] = __float22bfloat162_rn(make_float2(v1.z * inv, v1.w * inv));
    uint4 pk;
    pk.x = *reinterpret_cast<uint32_t*>(&h[0]);
    pk.y = *reinterpret_cast<uint32_t*>(&h[1]);
    pk.z = *reinterpret_cast<uint32_t*>(&h[2]);
    pk.w = *reinterpret_cast<uint32_t*>(&h[3]);
    *reinterpret_cast<uint4*>(&g_xb[(size_t)row * D_DIM + tid * 8]) = pk;
}

// ---------------------------------------------------------------------------
// Kernel 2: fused bf16 HMMA Gram tile + masked loss epilogue.
// UPPER-TRIANGULAR tiles only (528); off-diag tiles do row-side AND col-side
// epilogue passes (symmetry). C staged to SMEM (reuses operand buffers).
// ---------------------------------------------------------------------------
#define NCHUNK 32          // 2048 / 64
#define META   2048        // 4 label arrays x 512B
#define AOFF0 (META)
#define AOFF1 (META + 16384)
#define BOFF0 (META + 32768)
#define BOFF1 (META + 49152)
#define CBUF  (META)       // 64KB fp32 C tile, overlays operand buffers
#define SMEM_TOTAL (META + 65536)

__global__ __launch_bounds__(256, 2) void fused_loss_kernel(
    const int* __restrict__ targets, const int* __restrict__ sub) {

    extern __shared__ char smem[];
    const uint32_t sbase = smem_u32(smem);
    const int tid  = threadIdx.x;
    const int lane = tid & 31;
    const int wid  = tid >> 5;
    const int warp_m = wid & 1;
    const int warp_n = wid >> 1;

    // Triangular decode: t -> (bi, bj), 0 <= bi <= bj < 32
    const int t = blockIdx.x;
    int bj = (int)((sqrtf(8.0f * (float)t + 1.0f) - 1.0f) * 0.5f);
    while ((bj + 1) * (bj + 2) / 2 <= t) ++bj;
    while (bj * (bj + 1) / 2 > t) --bj;
    const int bi = t - bj * (bj + 1) / 2;
    const int row0 = bi * 128;
    const int col0 = bj * 128;
    const bool diag = (bi == bj);

    int* s_tgti = reinterpret_cast<int*>(smem + 0);
    int* s_subi = reinterpret_cast<int*>(smem + 512);
    int* s_tgtj = reinterpret_cast<int*>(smem + 1024);
    int* s_subj = reinterpret_cast<int*>(smem + 1536);
    if (tid < 128) {
        s_tgti[tid] = targets[row0 + tid];
        s_subi[tid] = sub[row0 + tid];
    } else {
        const int k = tid - 128;
        s_tgtj[k] = targets[col0 + k];
        s_subj[k] = sub[col0 + k];
    }

    float c[4][4][4];
    #pragma unroll
    for (int i = 0; i < 4; ++i)
        #pragma unroll
        for (int j = 0; j < 4; ++j)
            #pragma unroll
            for (int k = 0; k < 4; ++k) c[i][j][k] = 0.f;

    auto load_chunk = [&](int cc, int buf) {
        const uint32_t aOff = buf ? AOFF1 : AOFF0;
        const uint32_t bOff = buf ? BOFF1 : BOFF0;
        #pragma unroll
        for (int i = 0; i < 4; ++i) {
            const int idx = tid + i * 256;      // 0..1023
            const int r  = idx >> 3;
            const int kc = idx & 7;
            const uint32_t soff = SWZ((uint32_t)(idx * 16));
            cp16(sbase + aOff + soff, g_xb + (size_t)(row0 + r) * D_DIM + cc * 64 + kc * 8);
            if (!diag)
                cp16(sbase + bOff + soff, g_xb + (size_t)(col0 + r) * D_DIM + cc * 64 + kc * 8);
        }
    };

    load_chunk(0, 0);
    cp_commit();

    for (int cc = 0; cc < NCHUNK; ++cc) {
        if (cc < NCHUNK - 1) {
            load_chunk(cc + 1, (cc + 1) & 1);
            cp_commit();
            cp_wait<1>();
        } else {
            cp_wait<0>();
        }
        __syncthreads();

        const uint32_t aBase = sbase + ((cc & 1) ? AOFF1 : AOFF0);
        const uint32_t bBase = diag ? aBase : (sbase + ((cc & 1) ? BOFF1 : BOFF0));

        const int lrow = (lane & 7) + ((lane >> 3) & 1) * 8;
        const int lkof = ((lane >> 4) & 1) * 16;

        #pragma unroll
        for (int ks = 0; ks < 4; ++ks) {
            uint32_t a[4][4];
            #pragma unroll
            for (int ma = 0; ma < 4; ++ma) {
                const uint32_t off = (uint32_t)((warp_m * 64 + ma * 16 + lrow) * 128
                                                + ks * 32 + lkof);
                ldsm_x4(a[ma][0], a[ma][1], a[ma][2], a[ma][3], aBase + SWZ(off));
            }
            uint32_t b[2][4];
            #pragma unroll
            for (int nb = 0; nb < 2; ++nb) {
                const uint32_t off = (uint32_t)((warp_n * 32 + nb * 16 + lrow) * 128
                                                + ks * 32 + lkof);
                ldsm_x4(b[nb][0], b[nb][1], b[nb][2], b[nb][3], bBase + SWZ(off));
            }
            #pragma unroll
            for (int ma = 0; ma < 4; ++ma) {
                #pragma unroll
                for (int nb = 0; nb < 2; ++nb) {
                    mma16816(c[ma][nb * 2 + 0], a[ma], b[nb][0], b[nb][2]);
                    mma16816(c[ma][nb * 2 + 1], a[ma], b[nb][1], b[nb][3]);
                }
            }
        }
        __syncthreads();
    }

    // ---- stage C to SMEM (operand buffers are dead now) --------------------
    // rotation: physical col = (j + 4*r) & 127  (even -> float2 stores stay aligned)
    float* Cb = reinterpret_cast<float*>(smem + CBUF);
    {
        const int gsel = lane >> 2;
        const int tig  = lane & 3;
        #pragma unroll
        for (int ma = 0; ma < 4; ++ma) {
            const int r0 = warp_m * 64 + ma * 16 + gsel;
            const int r1 = r0 + 8;
            #pragma unroll
            for (int na = 0; na < 4; ++na) {
                const int jj = warp_n * 32 + na * 8 + tig * 2;
                const int p0 = (jj + 4 * r0) & 127;
                const int p1 = (jj + 4 * r1) & 127;
                *reinterpret_cast<float2*>(&Cb[r0 * 128 + p0]) =
                    make_float2(c[ma][na][0], c[ma][na][1]);
                *reinterpret_cast<float2*>(&Cb[r1 * 128 + p1]) =
                    make_float2(c[ma][na][2], c[ma][na][3]);
            }
        }
    }
    __syncthreads();

    // ---- epilogue passes ---------------------------------------------------
    auto accum = [](float cij, int tii, int sii, int tjj, int sjj, float* acc) {
        const float d = sqrtf(fmaxf(2.0f - 2.0f * cij, 1e-12f));
        const bool same  = (tii == tjj);
        const bool intra = (sii == sjj);
        if (same) {
            if (intra) { acc[0] += fmaxf(d + (MARGIN_1 - ALPHA_1), 0.f); acc[1] += 1.f; }
            else       { acc[2] += fmaxf(d + (MARGIN_2 - ALPHA_2), 0.f); acc[3] += 1.f; }
        } else {
            const float alpha = intra ? ALPHA_1 : ALPHA_2;
            const float diff = alpha - d;
            if (diff > 0.f) {
                const float w = __expf(diff);   // TVAL = 1
                if (intra) { acc[4] += diff * w; acc[5] += w; }
                else       { acc[6] += diff * w; acc[7] += w; }
            }
        }
    };

    // Pass A: row side. thread pair (2 per row), 64 cols each.
    {
        const int row  = tid >> 1;
        const int half = tid & 1;
        const int ti = s_tgti[row], si = s_subi[row];
        float acc[8] = {0.f, 0.f, 0.f, 0.f, 0.f, 0.f, 0.f, 0.f};
        #pragma unroll 8
        for (int q = 0; q < 64; ++q) {
            const int j = half * 64 + q;
            if (diag && j == row) continue;
            const float cij = Cb[row * 128 + ((j + 4 * row) & 127)];
            accum(cij, ti, si, s_tgtj[j], s_subj[j], acc);
        }
        #pragma unroll
        for (int v = 0; v < 8; ++v)
            acc[v] += __shfl_down_sync(0xffffffffu, acc[v], 1, 2);
        if (!half) {
            float* a = g_acc + (size_t)(row0 + row) * 8;
            #pragma unroll
            for (int v = 0; v < 8; ++v) atomicAdd(a + v, acc[v]);
        }
    }

    // Pass B: col side (mirror), off-diagonal tiles only.
    if (!diag) {
        const int col  = tid >> 1;
        const int half = tid & 1;
        const int ti = s_tgtj[col], si = s_subj[col];
        float acc[8] = {0.f, 0.f, 0.f, 0.f, 0.f, 0.f, 0.f, 0.f};
        #pragma unroll 8
        for (int q = 0; q < 64; ++q) {
            const int r = half * 64 + q;
            const float cij = Cb[r * 128 + ((col + 4 * r) & 127)];
            accum(cij, ti, si, s_tgti[r], s_subi[r], acc);
        }
        #pragma unroll
        for (int v = 0; v < 8; ++v)
            acc[v] += __shfl_down_sync(0xffffffffu, acc[v], 1, 2);
        if (!half) {
            float* a = g_acc + (size_t)(col0 + col) * 8;
            #pragma unroll
            for (int v = 0; v < 8; ++v) atomicAdd(a + v, acc[v]);
        }
    }
}

// ---------------------------------------------------------------------------
// Kernel 3: per-row combine + mean (multi-block, atomic into out[0])
// ---------------------------------------------------------------------------
__global__ __launch_bounds__(256) void finalize_kernel(float* __restrict__ out) {
    const int tid = threadIdx.x;
    const int row = blockIdx.x * 256 + tid;
    const float* a = g_acc + (size_t)row * 8;
    float sum = a[0] / (a[1] + EPS_F)
              + a[2] / (a[3] + EPS_F)
              + a[4] / (a[5] + EPS_F)
              + a[6] / (a[7] + EPS_F);
    #pragma unroll
    for (int off = 16; off; off >>= 1)
        sum += __shfl_down_sync(0xffffffffu, sum, off);

    __shared__ float red[8];
    if ((tid & 31) == 0) red[tid >> 5] = sum;
    __syncthreads();
    if (tid == 0) {
        float tot = 0.f;
        #pragma unroll
        for (int w = 0; w < 8; ++w) tot += red[w];
        atomicAdd(out, tot / (float)N_ROWS);
    }
}

// ---------------------------------------------------------------------------
// Launch
// ---------------------------------------------------------------------------
extern "C" void kernel_launch(void* const* d_in, const int* in_sizes, int n_in,
                              void* d_out, int out_size) {
    const float* x       = (const float*)d_in[0];
    const int*   targets = (const int*)d_in[1];
    const int*   sub     = (const int*)d_in[2];
    float*       out     = (float*)d_out;

    cudaFuncSetAttribute(fused_loss_kernel,
                         cudaFuncAttributeMaxDynamicSharedMemorySize, SMEM_TOTAL);

    zero_acc_kernel<<<(N_ROWS * 8 + 255) / 256, 256>>>(out);
    normalize_kernel<<<N_ROWS, 256>>>(x);
    const int ntiles = 32 * 33 / 2;   // 528 upper-triangular tiles
    fused_loss_kernel<<<ntiles, 256, SMEM_TOTAL>>>(targets, sub);
    finalize_kernel<<<N_ROWS / 256, 256>>>(out);
}